// round 13
// baseline (speedup 1.0000x reference)
#include <cuda_runtime.h>
#include <cstdint>

// CausalWindowedAttention: B=2,H=16,S=2048,D=64, window=256, temp=8
// Output = concat(out[B,H,S,D], attn[B,H,S,S]) as float32.
// Round-12 structure; Q/K/V loaded via cp.async.bulk (per-row, mbarrier
// completion: phase0=Q+K, phase1=V) instead of per-16B cp.async.
// Head key rows (j<0) zeroed once; tail garbage row only read masked.

#define SQ    2048
#define DH    64
#define MT    64              // queries per CTA tile
#define WIN   256
#define KRA   320             // key rows resident (reads clamped to row 319)
#define KPAD  68              // padded K/V row (floats), conflict-free LDS.128
#define SROW  268             // score row stride: 4 slack + up to 264 offsets
#define NTH   512

// smem layout (floats)
#define SM_Q   0
#define SM_K   (MT * DH)                  // 4096
#define SM_S   (SM_K + KRA * KPAD)        // 25856
#define SM_Z   (SM_S + MT * SROW)         // 43008
#define SM_MB  (SM_Z + 2048)              // 45056 (8B-aligned mbarrier)
#define SM_TOT (SM_MB + 4)                // 45060 floats = 180240 B

typedef unsigned long long ull;

__device__ __forceinline__ void ffma2(ull& d, ull a, ull b) {
    asm("fma.rn.f32x2 %0, %1, %2, %0;" : "+l"(d) : "l"(a), "l"(b));
}
__device__ __forceinline__ ull pk2(float x) {
    ull r;
    asm("mov.b64 %0, {%1, %1};" : "=l"(r) : "f"(x));
    return r;
}
__device__ __forceinline__ float unpk_sum(ull a) {
    float lo, hi;
    asm("mov.b64 {%0, %1}, %2;" : "=f"(lo), "=f"(hi) : "l"(a));
    return lo + hi;
}
__device__ __forceinline__ uint32_t s2u(const void* p) {
    return (uint32_t)__cvta_generic_to_shared(p);
}
__device__ __forceinline__ void bulk_store(void* gdst, uint32_t ssrc, uint32_t bytes) {
    asm volatile("cp.async.bulk.global.shared::cta.bulk_group [%0], [%1], %2;"
                 :: "l"(gdst), "r"(ssrc), "r"(bytes) : "memory");
}
__device__ __forceinline__ void bulk_load(uint32_t sdst, const void* gsrc,
                                          uint32_t bytes, uint32_t mbar) {
    asm volatile("cp.async.bulk.shared::cluster.global.mbarrier::complete_tx::bytes "
                 "[%0], [%1], %2, [%3];"
                 :: "r"(sdst), "l"(gsrc), "r"(bytes), "r"(mbar) : "memory");
}
__device__ __forceinline__ void fence_async() {
    asm volatile("fence.proxy.async.shared::cta;" ::: "memory");
}
__device__ __forceinline__ void mbar_init(uint32_t mbar, uint32_t cnt) {
    asm volatile("mbarrier.init.shared.b64 [%0], %1;" :: "r"(mbar), "r"(cnt) : "memory");
}
__device__ __forceinline__ void mbar_arrive_expect(uint32_t mbar, uint32_t bytes) {
    asm volatile("mbarrier.arrive.expect_tx.shared.b64 _, [%0], %1;"
                 :: "r"(mbar), "r"(bytes) : "memory");
}
__device__ __forceinline__ void mbar_wait(uint32_t mbar, uint32_t parity) {
    uint32_t done = 0;
    while (!done) {
        asm volatile(
            "{\n\t.reg .pred p;\n\t"
            "mbarrier.try_wait.parity.shared.b64 p, [%1], %2;\n\t"
            "selp.b32 %0, 1, 0, p;\n\t}"
            : "=r"(done) : "r"(mbar), "r"(parity) : "memory");
    }
}

__global__ void __launch_bounds__(NTH, 1)
cwa_kernel(const float* __restrict__ q,
           const float* __restrict__ k,
           const float* __restrict__ v,
           float* __restrict__ out,    // [BH, SQ, DH]
           float* __restrict__ attn)   // [BH, SQ, SQ]
{
    extern __shared__ float sm[];
    float* sQ = sm + SM_Q;   // Q tile; reused as PV combine buffer
    float* sK = sm + SM_K;   // K tile; reused for V
    float* sS = sm + SM_S;   // 64 rows x SROW; row m offsets indexed [-4, 264)
    float* sZ = sm + SM_Z;   // 2048 zero floats
    const uint32_t mb = s2u(sm + SM_MB);

    const int tile = blockIdx.x;
    const int bh   = blockIdx.y;
    const int i0   = tile * MT;
    const int tid  = threadIdx.x;
    const int lane = tid & 31;
    const int w    = tid >> 5;           // 0..15

    const size_t base = (size_t)bh * SQ * DH;
    const size_t attn_base = (size_t)bh * SQ * SQ;
    const int jn0 = i0 - (WIN - 1);      // key j for smem key-row n: j = jn0 + n

    // key rows with valid gmem backing: n in [n_lo, n_hi)
    const int n_lo = max(0, -jn0);
    const int n_hi = min(KRA, SQ - jn0);

    // ---- mbarrier init + zero buffer ----
    if (tid == 0)
        mbar_init(mb, 1);
    {
        const float4 z4 = make_float4(0.f, 0.f, 0.f, 0.f);
        float4* zs = (float4*)sZ;
        for (int idx = tid; idx < 2048 / 4; idx += NTH)
            zs[idx] = z4;
    }
    __syncthreads();    // mbarrier + sZ visible CTA-wide

    // ---- issue Q + K bulk loads (phase 0) ----
    if (tid < 64) {
        #pragma unroll
        for (int r5 = 0; r5 < 5; r5++) {
            const int n = tid * 5 + r5;
            if (n >= n_lo && n < n_hi)
                bulk_load(s2u(&sK[n * KPAD]),
                          k + base + (size_t)(jn0 + n) * DH, DH * 4, mb);
        }
    } else if (tid == 64) {
        bulk_load(s2u(sQ), q + base + (size_t)i0 * DH, MT * DH * 4, mb);
    }
    if (tid == 0)
        mbar_arrive_expect(mb, (uint32_t)(n_hi - n_lo) * (DH * 4)
                               + (uint32_t)(MT * DH * 4));

    // ---- zero head key rows (j < 0): never written by K or V loads.
    //      Required so PV's 0*V products stay 0 (uninit smem could be NaN).
    for (int idx = tid; idx < n_lo * KPAD; idx += NTH)
        sK[idx] = 0.f;

    // ---- merged zero bulk stores: suffix(i)+prefix(i+1) contiguous, 65 ops ----
    if (tid < MT) {
        const int m = tid;
        const int i = i0 + m;
        const int jlo = max(0, i - (WIN - 1));
        const int jstart4 = jlo & ~3;
        const int jend4 = (i + 4) & ~3;           // exclusive, multiple of 4
        float* row = attn + attn_base + (size_t)i * SQ;
        const uint32_t zaddr = s2u(sZ);
        fence_async();
        if (m == 0) {                              // first row's own prefix
            const uint32_t pb = (uint32_t)jstart4 * 4u;
            if (pb) bulk_store(row, zaddr, pb);
        }
        if (m < MT - 1) {                          // suffix(i) + prefix(i+1)
            const int jstart4_n = (max(0, i + 1 - (WIN - 1))) & ~3;
            const uint32_t bytes = (uint32_t)(SQ - jend4 + jstart4_n) * 4u;
            if (bytes) bulk_store(row + jend4, zaddr, bytes);
        } else {                                   // last row: suffix only
            const uint32_t sb = (uint32_t)(SQ - jend4) * 4u;
            if (sb) bulk_store(row + jend4, zaddr, sb);
        }
    }

    mbar_wait(mb, 0);
    __syncthreads();    // Q, K resident (incl. zeroed head rows)

    // ---- QK: warp w -> rows m0..m0+3, keys n = m0 + lane + 32*ni ----
    const int m0 = w * 4;
    ull acc[4][9];
    {
        #pragma unroll
        for (int mi = 0; mi < 4; mi++)
            #pragma unroll
            for (int ni = 0; ni < 9; ni++)
                acc[mi][ni] = 0ULL;

        int nb[9];
        #pragma unroll
        for (int ni = 0; ni < 9; ni++)
            nb[ni] = min(m0 + lane + 32 * ni, KRA - 1) * KPAD;  // clamp masked tail

        #pragma unroll 1
        for (int dc = 0; dc < DH / 4; dc++) {
            ulonglong2 q2[4];
            #pragma unroll
            for (int mi = 0; mi < 4; mi++)
                q2[mi] = *(const ulonglong2*)&sQ[(m0 + mi) * DH + dc * 4];
            // chunk 1: groups 0..3 (limits live k2 regs -> deeper pipelining)
            {
                ulonglong2 k2[4];
                #pragma unroll
                for (int ni = 0; ni < 4; ni++)
                    k2[ni] = *(const ulonglong2*)&sK[nb[ni] + dc * 4];
                #pragma unroll
                for (int ni = 0; ni < 4; ni++)
                    #pragma unroll
                    for (int mi = 0; mi < 4; mi++) {
                        ffma2(acc[mi][ni], q2[mi].x, k2[ni].x);
                        ffma2(acc[mi][ni], q2[mi].y, k2[ni].y);
                    }
            }
            // chunk 2: groups 4..8
            {
                ulonglong2 k2[5];
                #pragma unroll
                for (int ni = 0; ni < 5; ni++)
                    k2[ni] = *(const ulonglong2*)&sK[nb[ni + 4] + dc * 4];
                #pragma unroll
                for (int ni = 0; ni < 5; ni++)
                    #pragma unroll
                    for (int mi = 0; mi < 4; mi++) {
                        ffma2(acc[mi][ni + 4], q2[mi].x, k2[ni].x);
                        ffma2(acc[mi][ni + 4], q2[mi].y, k2[ni].y);
                    }
            }
        }
    }
    __syncthreads();   // all QK reads of sK done (acc lives in registers)

    // ---- issue V bulk loads NOW (phase 1): epilogue shadows the drain ----
    if (tid < 64) {
        #pragma unroll
        for (int r5 = 0; r5 < 5; r5++) {
            const int n = tid * 5 + r5;
            if (n >= n_lo && n < n_hi)
                bulk_load(s2u(&sK[n * KPAD]),
                          v + base + (size_t)(jn0 + n) * DH, DH * 4, mb);
        }
    }
    if (tid == 0)
        mbar_arrive_expect(mb, (uint32_t)(n_hi - n_lo) * (DH * 4));

    // ---- epilogue: fixed-shift exp, sum, store p; self-zeroes the row ----
    {
        #pragma unroll
        for (int mi = 0; mi < 4; mi++) {
            const int m = m0 + mi;
            const int i = i0 + m;
            const int jlo = max(0, i - (WIN - 1));
            const int s = (jlo & ~3) - jn0;
            const int off_lo = jlo & 3;
            const int off_hi = i - (jlo & ~3);
            float* rp = sS + m * SROW + 4;

            // head slack [-4, m0-s): stores below cover from max(-4, m0-s)
            const int cnt = min(max(m0 - s + 4, 0), 8);
            if (lane < cnt)
                rp[-4 + lane] = 0.f;

            float sc[9];
            float sum = 0.f;
            #pragma unroll
            for (int ni = 0; ni < 9; ni++) {
                const int off = m0 + lane + 32 * ni - s;
                const bool ok = (off >= off_lo) && (off <= off_hi);
                float e = ok ? __expf(unpk_sum(acc[mi][ni]) * 0.125f) : 0.f;
                sc[ni] = e;
                sum += e;
            }
            #pragma unroll
            for (int o = 16; o; o >>= 1)
                sum += __shfl_xor_sync(0xffffffffu, sum, o);

            const float inv = 1.f / sum;
            #pragma unroll
            for (int ni = 0; ni < 9; ni++) {
                const int off = m0 + lane + 32 * ni - s;
                // stores zeros outside the band too: covers [max(-4,m0-s), 263]
                if ((unsigned)(off + 4) < (unsigned)SROW)
                    rp[off] = sc[ni] * inv;
            }
        }
    }

    // ---- band bulk stores: warp-local rows, issue immediately ----
    __syncwarp();
    if (lane < 4) {
        const int m = m0 + lane;
        const int i = i0 + m;
        const int jlo = max(0, i - (WIN - 1));
        const int jstart4 = jlo & ~3;
        const int jend4 = (i + 4) & ~3;
        fence_async();
        bulk_store(attn + attn_base + (size_t)i * SQ + jstart4,
                   s2u(sS + m * SROW + 4),
                   (uint32_t)(jend4 - jstart4) * 4u);
    }

    mbar_wait(mb, 1);  // V resident (drain mostly shadowed by epilogue)
    __syncthreads();   // all p rows + V visible for PV

    // ---- PV: thread owns 4 rows (grp) x 1 d-quad (dq) x half keys (kh) ----
    {
        const int dq  = tid & 15;         // d cols dq*4..dq*4+3
        const int grp = (tid >> 4) & 15;  // rows grp*4..grp*4+3
        const int kh  = tid >> 8;         // key half
        const int r0  = grp * 4;

        int sr[4];
        #pragma unroll
        for (int rr = 0; rr < 4; rr++)
            sr[rr] = (max(0, i0 + r0 + rr - (WIN - 1)) & ~3) - jn0;

        const int nbase = sr[3] - 4;            // ≡ 3 mod 4; aligned p4 loads
        const int nend  = r0 + 258;             // inclusive
        const int iters = (nend - nbase + 1) >> 2;
        const int ih    = (iters + 1) >> 1;
        const int itlo  = kh ? ih : 0;
        const int ithi  = kh ? iters : ih;

        const float* rp0 = sS + (r0 + 0) * SROW + 4 - sr[0];
        const float* rp1 = sS + (r0 + 1) * SROW + 4 - sr[1];
        const float* rp2 = sS + (r0 + 2) * SROW + 4 - sr[2];
        const float* rp3 = sS + (r0 + 3) * SROW + 4 - sr[3];

        ull ax[4], az[4];
        #pragma unroll
        for (int rr = 0; rr < 4; rr++) { ax[rr] = 0ULL; az[rr] = 0ULL; }

        #pragma unroll 1
        for (int it = itlo; it < ithi; it++) {
            const int n = nbase + 4 * it;
            const float4 p0 = *(const float4*)&rp0[n];
            const float4 p1 = *(const float4*)&rp1[n];
            const float4 p2 = *(const float4*)&rp2[n];
            const float4 p3 = *(const float4*)&rp3[n];
            #pragma unroll
            for (int c = 0; c < 4; c++) {
                ulonglong2 v2 = *(const ulonglong2*)&sK[(n + c) * KPAD + dq * 4];
                ull pc0 = pk2((&p0.x)[c]);
                ull pc1 = pk2((&p1.x)[c]);
                ull pc2 = pk2((&p2.x)[c]);
                ull pc3 = pk2((&p3.x)[c]);
                ffma2(ax[0], pc0, v2.x); ffma2(az[0], pc0, v2.y);
                ffma2(ax[1], pc1, v2.x); ffma2(az[1], pc1, v2.y);
                ffma2(ax[2], pc2, v2.x); ffma2(az[2], pc2, v2.y);
                ffma2(ax[3], pc3, v2.x); ffma2(az[3], pc3, v2.y);
            }
        }

        // combine halves through sQ (Q consumed; 64 rows x 64 d = 16KB)
        if (kh == 0) {
            #pragma unroll
            for (int rr = 0; rr < 4; rr++) {
                ulonglong2 o;
                o.x = ax[rr]; o.y = az[rr];
                *(ulonglong2*)&sQ[(r0 + rr) * DH + dq * 4] = o;
            }
        }
        __syncthreads();
        if (kh == 1) {
            #pragma unroll
            for (int rr = 0; rr < 4; rr++) {
                float4 part = *(const float4*)&sQ[(r0 + rr) * DH + dq * 4];
                float lo0, hi0, lo1, hi1;
                asm("mov.b64 {%0, %1}, %2;" : "=f"(lo0), "=f"(hi0) : "l"(ax[rr]));
                asm("mov.b64 {%0, %1}, %2;" : "=f"(lo1), "=f"(hi1) : "l"(az[rr]));
                float4 mine;
                mine.x = lo0 + part.x; mine.y = hi0 + part.y;
                mine.z = lo1 + part.z; mine.w = hi1 + part.w;
                *(float4*)(out + base + (size_t)(i0 + r0 + rr) * DH + dq * 4) = mine;
            }
        }
    }

    // ---- ensure all bulk stores complete before kernel end ----
    asm volatile("cp.async.bulk.commit_group;" ::: "memory");
    asm volatile("cp.async.bulk.wait_group 0;" ::: "memory");
}

extern "C" void kernel_launch(void* const* d_in, const int* in_sizes, int n_in,
                              void* d_out, int out_size)
{
    const float* q = (const float*)d_in[0];
    const float* k = (const float*)d_in[1];
    const float* v = (const float*)d_in[2];

    const int BH = in_sizes[0] / (SQ * DH);   // 32

    float* out  = (float*)d_out;
    float* attn = out + (size_t)BH * SQ * DH;

    cudaFuncSetAttribute(cwa_kernel,
                         cudaFuncAttributeMaxDynamicSharedMemorySize,
                         SM_TOT * (int)sizeof(float));

    dim3 grid(SQ / MT, BH);
    cwa_kernel<<<grid, NTH, SM_TOT * sizeof(float)>>>(q, k, v, out, attn);
    (void)n_in; (void)out_size;
}

// round 14
// speedup vs baseline: 1.1780x; 1.1780x over previous
#include <cuda_runtime.h>
#include <cstdint>

// CausalWindowedAttention: B=2,H=16,S=2048,D=64, window=256, temp=8
// Output = concat(out[B,H,S,D], attn[B,H,S,S]) as float32.
// Round-12 structure; Q and V loaded with ONE cp.async.bulk each (V stored
// DENSE, stride 64 — PV reads rows so no conflicts), K via padded cp.async
// (column access needs the 68-float pitch). attn zeros + band via TMA.

#define SQ    2048
#define DH    64
#define MT    64              // queries per CTA tile
#define WIN   256
#define KRA   320             // key rows resident (reads clamped to row 319)
#define KPAD  68              // padded K row (floats), conflict-free LDS.128
#define SROW  268             // score row stride: 4 slack + up to 264 offsets
#define NTH   512

// smem layout (floats)
#define SM_Q   0
#define SM_K   (MT * DH)                  // 4096  (K padded; V dense alias)
#define SM_S   (SM_K + KRA * KPAD)        // 25856
#define SM_Z   (SM_S + MT * SROW)         // 43008
#define SM_MB  (SM_Z + 2048)              // 45056 (8B-aligned mbarrier)
#define SM_TOT (SM_MB + 4)                // 45060 floats = 180240 B

typedef unsigned long long ull;

__device__ __forceinline__ void ffma2(ull& d, ull a, ull b) {
    asm("fma.rn.f32x2 %0, %1, %2, %0;" : "+l"(d) : "l"(a), "l"(b));
}
__device__ __forceinline__ ull pk2(float x) {
    ull r;
    asm("mov.b64 %0, {%1, %1};" : "=l"(r) : "f"(x));
    return r;
}
__device__ __forceinline__ float unpk_sum(ull a) {
    float lo, hi;
    asm("mov.b64 {%0, %1}, %2;" : "=f"(lo), "=f"(hi) : "l"(a));
    return lo + hi;
}
__device__ __forceinline__ uint32_t s2u(const void* p) {
    return (uint32_t)__cvta_generic_to_shared(p);
}
__device__ __forceinline__ void bulk_store(void* gdst, uint32_t ssrc, uint32_t bytes) {
    asm volatile("cp.async.bulk.global.shared::cta.bulk_group [%0], [%1], %2;"
                 :: "l"(gdst), "r"(ssrc), "r"(bytes) : "memory");
}
__device__ __forceinline__ void bulk_load(uint32_t sdst, const void* gsrc,
                                          uint32_t bytes, uint32_t mbar) {
    asm volatile("cp.async.bulk.shared::cluster.global.mbarrier::complete_tx::bytes "
                 "[%0], [%1], %2, [%3];"
                 :: "r"(sdst), "l"(gsrc), "r"(bytes), "r"(mbar) : "memory");
}
__device__ __forceinline__ void fence_async() {
    asm volatile("fence.proxy.async.shared::cta;" ::: "memory");
}
__device__ __forceinline__ void cp16(uint32_t sdst, const void* gsrc, uint32_t sz) {
    asm volatile("cp.async.cg.shared.global [%0], [%1], 16, %2;"
                 :: "r"(sdst), "l"(gsrc), "r"(sz) : "memory");
}
__device__ __forceinline__ void cp_commit() {
    asm volatile("cp.async.commit_group;" ::: "memory");
}
__device__ __forceinline__ void cp_wait0() {
    asm volatile("cp.async.wait_group 0;" ::: "memory");
}
__device__ __forceinline__ void mbar_init(uint32_t mbar, uint32_t cnt) {
    asm volatile("mbarrier.init.shared.b64 [%0], %1;" :: "r"(mbar), "r"(cnt) : "memory");
}
__device__ __forceinline__ void mbar_arrive_expect(uint32_t mbar, uint32_t bytes) {
    asm volatile("mbarrier.arrive.expect_tx.shared.b64 _, [%0], %1;"
                 :: "r"(mbar), "r"(bytes) : "memory");
}
__device__ __forceinline__ void mbar_wait(uint32_t mbar, uint32_t parity) {
    uint32_t done = 0;
    while (!done) {
        asm volatile(
            "{\n\t.reg .pred p;\n\t"
            "mbarrier.try_wait.parity.shared.b64 p, [%1], %2;\n\t"
            "selp.b32 %0, 1, 0, p;\n\t}"
            : "=r"(done) : "r"(mbar), "r"(parity) : "memory");
    }
}

__global__ void __launch_bounds__(NTH, 1)
cwa_kernel(const float* __restrict__ q,
           const float* __restrict__ k,
           const float* __restrict__ v,
           float* __restrict__ out,    // [BH, SQ, DH]
           float* __restrict__ attn)   // [BH, SQ, SQ]
{
    extern __shared__ float sm[];
    float* sQ = sm + SM_Q;   // Q tile; reused as PV combine buffer
    float* sK = sm + SM_K;   // K tile (padded); reused for V (DENSE, stride 64)
    float* sS = sm + SM_S;   // 64 rows x SROW; row m offsets indexed [-4, 264)
    float* sZ = sm + SM_Z;   // 2048 zero floats
    const uint32_t mb = s2u(sm + SM_MB);

    const int tile = blockIdx.x;
    const int bh   = blockIdx.y;
    const int i0   = tile * MT;
    const int tid  = threadIdx.x;
    const int lane = tid & 31;
    const int w    = tid >> 5;           // 0..15

    const size_t base = (size_t)bh * SQ * DH;
    const size_t attn_base = (size_t)bh * SQ * SQ;
    const int jn0 = i0 - (WIN - 1);      // key j for smem key-row n: j = jn0 + n

    // key rows with valid gmem backing: n in [n_lo, n_hi)
    const int n_lo = max(0, -jn0);
    const int n_hi = min(KRA, SQ - jn0);

    // ---- mbarrier init ----
    if (tid == 0)
        mbar_init(mb, 1);

    // ---- K window via cp.async, padded (zero-fill OOB via src_size=0) ----
    for (int idx = tid; idx < KRA * (DH / 4); idx += NTH) {
        int n = idx >> 4;
        int c = idx & 15;
        int j = jn0 + n;
        bool valid = (j >= 0 && j < SQ);
        const float* src = valid ? (k + base + (size_t)j * DH + c * 4) : (k + base);
        cp16(s2u(&sK[n * KPAD + c * 4]), src, valid ? 16u : 0u);
    }
    cp_commit();

    // ---- zero buffer (TMA zero-store source) ----
    {
        const float4 z4 = make_float4(0.f, 0.f, 0.f, 0.f);
        float4* zs = (float4*)sZ;
        for (int idx = tid; idx < 2048 / 4; idx += NTH)
            zs[idx] = z4;
    }
    __syncthreads();    // mbarrier + sZ visible CTA-wide

    // ---- Q: one 16KB bulk load (mbarrier phase 0) ----
    if (tid == 0) {
        mbar_arrive_expect(mb, (uint32_t)(MT * DH * 4));
        bulk_load(s2u(sQ), q + base + (size_t)i0 * DH,
                  (uint32_t)(MT * DH * 4), mb);
    }

    // ---- merged zero bulk stores: suffix(i)+prefix(i+1) contiguous, 65 ops ----
    if (tid < MT) {
        const int m = tid;
        const int i = i0 + m;
        const int jlo = max(0, i - (WIN - 1));
        const int jstart4 = jlo & ~3;
        const int jend4 = (i + 4) & ~3;           // exclusive, multiple of 4
        float* row = attn + attn_base + (size_t)i * SQ;
        const uint32_t zaddr = s2u(sZ);
        fence_async();
        if (m == 0) {                              // first row's own prefix
            const uint32_t pb = (uint32_t)jstart4 * 4u;
            if (pb) bulk_store(row, zaddr, pb);
        }
        if (m < MT - 1) {                          // suffix(i) + prefix(i+1)
            const int jstart4_n = (max(0, i + 1 - (WIN - 1))) & ~3;
            const uint32_t bytes = (uint32_t)(SQ - jend4 + jstart4_n) * 4u;
            if (bytes) bulk_store(row + jend4, zaddr, bytes);
        } else {                                   // last row: suffix only
            const uint32_t sb = (uint32_t)(SQ - jend4) * 4u;
            if (sb) bulk_store(row + jend4, zaddr, sb);
        }
    }

    cp_wait0();         // K resident
    mbar_wait(mb, 0);   // Q resident
    __syncthreads();

    // ---- QK: warp w -> rows m0..m0+3, keys n = m0 + lane + 32*ni ----
    const int m0 = w * 4;
    ull acc[4][9];
    {
        #pragma unroll
        for (int mi = 0; mi < 4; mi++)
            #pragma unroll
            for (int ni = 0; ni < 9; ni++)
                acc[mi][ni] = 0ULL;

        int nb[9];
        #pragma unroll
        for (int ni = 0; ni < 9; ni++)
            nb[ni] = min(m0 + lane + 32 * ni, KRA - 1) * KPAD;  // clamp masked tail

        #pragma unroll 1
        for (int dc = 0; dc < DH / 4; dc++) {
            ulonglong2 q2[4];
            #pragma unroll
            for (int mi = 0; mi < 4; mi++)
                q2[mi] = *(const ulonglong2*)&sQ[(m0 + mi) * DH + dc * 4];
            // chunk 1: groups 0..3 (limits live k2 regs -> deeper pipelining)
            {
                ulonglong2 k2[4];
                #pragma unroll
                for (int ni = 0; ni < 4; ni++)
                    k2[ni] = *(const ulonglong2*)&sK[nb[ni] + dc * 4];
                #pragma unroll
                for (int ni = 0; ni < 4; ni++)
                    #pragma unroll
                    for (int mi = 0; mi < 4; mi++) {
                        ffma2(acc[mi][ni], q2[mi].x, k2[ni].x);
                        ffma2(acc[mi][ni], q2[mi].y, k2[ni].y);
                    }
            }
            // chunk 2: groups 4..8
            {
                ulonglong2 k2[5];
                #pragma unroll
                for (int ni = 0; ni < 5; ni++)
                    k2[ni] = *(const ulonglong2*)&sK[nb[ni + 4] + dc * 4];
                #pragma unroll
                for (int ni = 0; ni < 5; ni++)
                    #pragma unroll
                    for (int mi = 0; mi < 4; mi++) {
                        ffma2(acc[mi][ni + 4], q2[mi].x, k2[ni].x);
                        ffma2(acc[mi][ni + 4], q2[mi].y, k2[ni].y);
                    }
            }
        }
    }
    __syncthreads();   // all QK reads of sK done (acc lives in registers)

    // ---- V: ONE dense bulk load into sK region (phase 1); head rows zeroed.
    //      Rows n_lo..n_hi-1 are contiguous in gmem: (n_hi-n_lo)*256 bytes.
    if (tid == 0) {
        mbar_arrive_expect(mb, (uint32_t)(n_hi - n_lo) * (DH * 4));
        bulk_load(s2u(&sK[n_lo * DH]),
                  v + base + (size_t)(jn0 + n_lo) * DH,
                  (uint32_t)(n_hi - n_lo) * (DH * 4), mb);
    }
    // head rows (j<0): p=0 there, but smem must be finite (0 * NaN = NaN)
    for (int idx = tid; idx < n_lo * DH; idx += NTH)
        sK[idx] = 0.f;

    // ---- epilogue: fixed-shift exp, sum, store p; self-zeroes the row ----
    {
        #pragma unroll
        for (int mi = 0; mi < 4; mi++) {
            const int m = m0 + mi;
            const int i = i0 + m;
            const int jlo = max(0, i - (WIN - 1));
            const int s = (jlo & ~3) - jn0;
            const int off_lo = jlo & 3;
            const int off_hi = i - (jlo & ~3);
            float* rp = sS + m * SROW + 4;

            // head slack [-4, m0-s): stores below cover from max(-4, m0-s)
            const int cnt = min(max(m0 - s + 4, 0), 8);
            if (lane < cnt)
                rp[-4 + lane] = 0.f;

            float sc[9];
            float sum = 0.f;
            #pragma unroll
            for (int ni = 0; ni < 9; ni++) {
                const int off = m0 + lane + 32 * ni - s;
                const bool ok = (off >= off_lo) && (off <= off_hi);
                float e = ok ? __expf(unpk_sum(acc[mi][ni]) * 0.125f) : 0.f;
                sc[ni] = e;
                sum += e;
            }
            #pragma unroll
            for (int o = 16; o; o >>= 1)
                sum += __shfl_xor_sync(0xffffffffu, sum, o);

            const float inv = 1.f / sum;
            #pragma unroll
            for (int ni = 0; ni < 9; ni++) {
                const int off = m0 + lane + 32 * ni - s;
                // stores zeros outside the band too: covers [max(-4,m0-s), 263]
                if ((unsigned)(off + 4) < (unsigned)SROW)
                    rp[off] = sc[ni] * inv;
            }
        }
    }

    // ---- band bulk stores: warp-local rows, issue immediately ----
    __syncwarp();
    if (lane < 4) {
        const int m = m0 + lane;
        const int i = i0 + m;
        const int jlo = max(0, i - (WIN - 1));
        const int jstart4 = jlo & ~3;
        const int jend4 = (i + 4) & ~3;
        fence_async();
        bulk_store(attn + attn_base + (size_t)i * SQ + jstart4,
                   s2u(sS + m * SROW + 4),
                   (uint32_t)(jend4 - jstart4) * 4u);
    }

    mbar_wait(mb, 1);  // V resident (drain shadowed by epilogue + band issue)
    __syncthreads();   // all p rows + zeroed head V rows visible for PV

    // ---- PV: thread owns 4 rows (grp) x 1 d-quad (dq) x half keys (kh).
    //      V is DENSE: row n at sK[n*64]. Negative n reads sQ tail (finite,
    //      p=0 there). Rows [0, n_lo) zeroed above.
    {
        const int dq  = tid & 15;         // d cols dq*4..dq*4+3
        const int grp = (tid >> 4) & 15;  // rows grp*4..grp*4+3
        const int kh  = tid >> 8;         // key half
        const int r0  = grp * 4;

        int sr[4];
        #pragma unroll
        for (int rr = 0; rr < 4; rr++)
            sr[rr] = (max(0, i0 + r0 + rr - (WIN - 1)) & ~3) - jn0;

        const int nbase = sr[3] - 4;            // ≡ 3 mod 4; aligned p4 loads
        const int nend  = r0 + 258;             // inclusive
        const int iters = (nend - nbase + 1) >> 2;
        const int ih    = (iters + 1) >> 1;
        const int itlo  = kh ? ih : 0;
        const int ithi  = kh ? iters : ih;

        const float* rp0 = sS + (r0 + 0) * SROW + 4 - sr[0];
        const float* rp1 = sS + (r0 + 1) * SROW + 4 - sr[1];
        const float* rp2 = sS + (r0 + 2) * SROW + 4 - sr[2];
        const float* rp3 = sS + (r0 + 3) * SROW + 4 - sr[3];

        ull ax[4], az[4];
        #pragma unroll
        for (int rr = 0; rr < 4; rr++) { ax[rr] = 0ULL; az[rr] = 0ULL; }

        #pragma unroll 1
        for (int it = itlo; it < ithi; it++) {
            const int n = nbase + 4 * it;
            const float4 p0 = *(const float4*)&rp0[n];
            const float4 p1 = *(const float4*)&rp1[n];
            const float4 p2 = *(const float4*)&rp2[n];
            const float4 p3 = *(const float4*)&rp3[n];
            #pragma unroll
            for (int c = 0; c < 4; c++) {
                ulonglong2 v2 = *(const ulonglong2*)&sK[(n + c) * DH + dq * 4];
                ull pc0 = pk2((&p0.x)[c]);
                ull pc1 = pk2((&p1.x)[c]);
                ull pc2 = pk2((&p2.x)[c]);
                ull pc3 = pk2((&p3.x)[c]);
                ffma2(ax[0], pc0, v2.x); ffma2(az[0], pc0, v2.y);
                ffma2(ax[1], pc1, v2.x); ffma2(az[1], pc1, v2.y);
                ffma2(ax[2], pc2, v2.x); ffma2(az[2], pc2, v2.y);
                ffma2(ax[3], pc3, v2.x); ffma2(az[3], pc3, v2.y);
            }
        }

        // combine halves through sQ (Q consumed; 64 rows x 64 d = 16KB)
        if (kh == 0) {
            #pragma unroll
            for (int rr = 0; rr < 4; rr++) {
                ulonglong2 o;
                o.x = ax[rr]; o.y = az[rr];
                *(ulonglong2*)&sQ[(r0 + rr) * DH + dq * 4] = o;
            }
        }
        __syncthreads();
        if (kh == 1) {
            #pragma unroll
            for (int rr = 0; rr < 4; rr++) {
                float4 part = *(const float4*)&sQ[(r0 + rr) * DH + dq * 4];
                float lo0, hi0, lo1, hi1;
                asm("mov.b64 {%0, %1}, %2;" : "=f"(lo0), "=f"(hi0) : "l"(ax[rr]));
                asm("mov.b64 {%0, %1}, %2;" : "=f"(lo1), "=f"(hi1) : "l"(az[rr]));
                float4 mine;
                mine.x = lo0 + part.x; mine.y = hi0 + part.y;
                mine.z = lo1 + part.z; mine.w = hi1 + part.w;
                *(float4*)(out + base + (size_t)(i0 + r0 + rr) * DH + dq * 4) = mine;
            }
        }
    }

    // ---- ensure all bulk stores complete before kernel end ----
    asm volatile("cp.async.bulk.commit_group;" ::: "memory");
    asm volatile("cp.async.bulk.wait_group 0;" ::: "memory");
}

extern "C" void kernel_launch(void* const* d_in, const int* in_sizes, int n_in,
                              void* d_out, int out_size)
{
    const float* q = (const float*)d_in[0];
    const float* k = (const float*)d_in[1];
    const float* v = (const float*)d_in[2];

    const int BH = in_sizes[0] / (SQ * DH);   // 32

    float* out  = (float*)d_out;
    float* attn = out + (size_t)BH * SQ * DH;

    cudaFuncSetAttribute(cwa_kernel,
                         cudaFuncAttributeMaxDynamicSharedMemorySize,
                         SM_TOT * (int)sizeof(float));

    dim3 grid(SQ / MT, BH);
    cwa_kernel<<<grid, NTH, SM_TOT * sizeof(float)>>>(q, k, v, out, attn);
    (void)n_in; (void)out_size;
}

// round 15
// speedup vs baseline: 1.2682x; 1.0765x over previous
#include <cuda_runtime.h>
#include <cstdint>

// CausalWindowedAttention: B=2,H=16,S=2048,D=64, window=256, temp=8
// Output = concat(out[B,H,S,D], attn[B,H,S,S]) as float32.
// Fully warp-local tail: warp w does QK+softmax+band-store+PV for rows
// 4w..4w+3 with the PV key-half split inside the warp (combine via shfl).
// No CTA syncs between epilogue and PV. Q/V single bulk loads; V dense.

#define SQ    2048
#define DH    64
#define MT    64              // queries per CTA tile
#define WIN   256
#define KRA   320             // key rows resident (reads clamped to row 319)
#define KPAD  68              // padded K row (floats), conflict-free LDS.128
#define SROW  268             // score row stride: 4 slack + up to 264 offsets
#define NTH   512

// smem layout (floats)
#define SM_Q   0
#define SM_K   (MT * DH)                  // 4096  (K padded; V dense alias)
#define SM_S   (SM_K + KRA * KPAD)        // 25856
#define SM_Z   (SM_S + MT * SROW)         // 43008
#define SM_MB  (SM_Z + 2048)              // 45056 (8B-aligned mbarrier)
#define SM_TOT (SM_MB + 4)                // 45060 floats = 180240 B

typedef unsigned long long ull;

__device__ __forceinline__ void ffma2(ull& d, ull a, ull b) {
    asm("fma.rn.f32x2 %0, %1, %2, %0;" : "+l"(d) : "l"(a), "l"(b));
}
__device__ __forceinline__ ull pk2(float x) {
    ull r;
    asm("mov.b64 %0, {%1, %1};" : "=l"(r) : "f"(x));
    return r;
}
__device__ __forceinline__ float unpk_sum(ull a) {
    float lo, hi;
    asm("mov.b64 {%0, %1}, %2;" : "=f"(lo), "=f"(hi) : "l"(a));
    return lo + hi;
}
__device__ __forceinline__ uint32_t s2u(const void* p) {
    return (uint32_t)__cvta_generic_to_shared(p);
}
__device__ __forceinline__ void bulk_store(void* gdst, uint32_t ssrc, uint32_t bytes) {
    asm volatile("cp.async.bulk.global.shared::cta.bulk_group [%0], [%1], %2;"
                 :: "l"(gdst), "r"(ssrc), "r"(bytes) : "memory");
}
__device__ __forceinline__ void bulk_load(uint32_t sdst, const void* gsrc,
                                          uint32_t bytes, uint32_t mbar) {
    asm volatile("cp.async.bulk.shared::cluster.global.mbarrier::complete_tx::bytes "
                 "[%0], [%1], %2, [%3];"
                 :: "r"(sdst), "l"(gsrc), "r"(bytes), "r"(mbar) : "memory");
}
__device__ __forceinline__ void fence_async() {
    asm volatile("fence.proxy.async.shared::cta;" ::: "memory");
}
__device__ __forceinline__ void cp16(uint32_t sdst, const void* gsrc, uint32_t sz) {
    asm volatile("cp.async.cg.shared.global [%0], [%1], 16, %2;"
                 :: "r"(sdst), "l"(gsrc), "r"(sz) : "memory");
}
__device__ __forceinline__ void cp_commit() {
    asm volatile("cp.async.commit_group;" ::: "memory");
}
__device__ __forceinline__ void cp_wait0() {
    asm volatile("cp.async.wait_group 0;" ::: "memory");
}
__device__ __forceinline__ void mbar_init(uint32_t mbar, uint32_t cnt) {
    asm volatile("mbarrier.init.shared.b64 [%0], %1;" :: "r"(mbar), "r"(cnt) : "memory");
}
__device__ __forceinline__ void mbar_arrive_expect(uint32_t mbar, uint32_t bytes) {
    asm volatile("mbarrier.arrive.expect_tx.shared.b64 _, [%0], %1;"
                 :: "r"(mbar), "r"(bytes) : "memory");
}
__device__ __forceinline__ void mbar_wait(uint32_t mbar, uint32_t parity) {
    uint32_t done = 0;
    while (!done) {
        asm volatile(
            "{\n\t.reg .pred p;\n\t"
            "mbarrier.try_wait.parity.shared.b64 p, [%1], %2;\n\t"
            "selp.b32 %0, 1, 0, p;\n\t}"
            : "=r"(done) : "r"(mbar), "r"(parity) : "memory");
    }
}

__global__ void __launch_bounds__(NTH, 1)
cwa_kernel(const float* __restrict__ q,
           const float* __restrict__ k,
           const float* __restrict__ v,
           float* __restrict__ out,    // [BH, SQ, DH]
           float* __restrict__ attn)   // [BH, SQ, SQ]
{
    extern __shared__ float sm[];
    float* sQ = sm + SM_Q;   // Q tile; reused as out-tile staging for TMA
    float* sK = sm + SM_K;   // K tile (padded); reused for V (DENSE, stride 64)
    float* sS = sm + SM_S;   // 64 rows x SROW; row m offsets indexed [-4, 264)
    float* sZ = sm + SM_Z;   // 2048 zero floats
    const uint32_t mb = s2u(sm + SM_MB);

    const int tile = blockIdx.x;
    const int bh   = blockIdx.y;
    const int i0   = tile * MT;
    const int tid  = threadIdx.x;
    const int lane = tid & 31;
    const int w    = tid >> 5;           // 0..15

    const size_t base = (size_t)bh * SQ * DH;
    const size_t attn_base = (size_t)bh * SQ * SQ;
    const int jn0 = i0 - (WIN - 1);      // key j for smem key-row n: j = jn0 + n

    // key rows with valid gmem backing: n in [n_lo, n_hi)
    const int n_lo = max(0, -jn0);
    const int n_hi = min(KRA, SQ - jn0);

    // ---- mbarrier init ----
    if (tid == 0)
        mbar_init(mb, 1);

    // ---- K window via cp.async, padded (zero-fill OOB via src_size=0) ----
    for (int idx = tid; idx < KRA * (DH / 4); idx += NTH) {
        int n = idx >> 4;
        int c = idx & 15;
        int j = jn0 + n;
        bool valid = (j >= 0 && j < SQ);
        const float* src = valid ? (k + base + (size_t)j * DH + c * 4) : (k + base);
        cp16(s2u(&sK[n * KPAD + c * 4]), src, valid ? 16u : 0u);
    }
    cp_commit();

    // ---- zero buffer (TMA zero-store source) ----
    {
        const float4 z4 = make_float4(0.f, 0.f, 0.f, 0.f);
        float4* zs = (float4*)sZ;
        for (int idx = tid; idx < 2048 / 4; idx += NTH)
            zs[idx] = z4;
    }
    __syncthreads();    // mbarrier + sZ visible CTA-wide

    // ---- Q: one 16KB bulk load (mbarrier phase 0) ----
    if (tid == 0) {
        mbar_arrive_expect(mb, (uint32_t)(MT * DH * 4));
        bulk_load(s2u(sQ), q + base + (size_t)i0 * DH,
                  (uint32_t)(MT * DH * 4), mb);
    }

    // ---- merged zero bulk stores: suffix(i)+prefix(i+1) contiguous, 65 ops ----
    if (tid < MT) {
        const int m = tid;
        const int i = i0 + m;
        const int jlo = max(0, i - (WIN - 1));
        const int jstart4 = jlo & ~3;
        const int jend4 = (i + 4) & ~3;           // exclusive, multiple of 4
        float* row = attn + attn_base + (size_t)i * SQ;
        const uint32_t zaddr = s2u(sZ);
        fence_async();
        if (m == 0) {                              // first row's own prefix
            const uint32_t pb = (uint32_t)jstart4 * 4u;
            if (pb) bulk_store(row, zaddr, pb);
        }
        if (m < MT - 1) {                          // suffix(i) + prefix(i+1)
            const int jstart4_n = (max(0, i + 1 - (WIN - 1))) & ~3;
            const uint32_t bytes = (uint32_t)(SQ - jend4 + jstart4_n) * 4u;
            if (bytes) bulk_store(row + jend4, zaddr, bytes);
        } else {                                   // last row: suffix only
            const uint32_t sb = (uint32_t)(SQ - jend4) * 4u;
            if (sb) bulk_store(row + jend4, zaddr, sb);
        }
    }

    cp_wait0();         // K resident
    mbar_wait(mb, 0);   // Q resident
    __syncthreads();

    // ---- QK: warp w -> rows m0..m0+3, keys n = m0 + lane + 32*ni ----
    const int m0 = w * 4;
    ull acc[4][9];
    {
        #pragma unroll
        for (int mi = 0; mi < 4; mi++)
            #pragma unroll
            for (int ni = 0; ni < 9; ni++)
                acc[mi][ni] = 0ULL;

        int nb[9];
        #pragma unroll
        for (int ni = 0; ni < 9; ni++)
            nb[ni] = min(m0 + lane + 32 * ni, KRA - 1) * KPAD;  // clamp masked tail

        #pragma unroll 1
        for (int dc = 0; dc < DH / 4; dc++) {
            ulonglong2 q2[4];
            #pragma unroll
            for (int mi = 0; mi < 4; mi++)
                q2[mi] = *(const ulonglong2*)&sQ[(m0 + mi) * DH + dc * 4];
            // chunk 1: groups 0..3 (limits live k2 regs -> deeper pipelining)
            {
                ulonglong2 k2[4];
                #pragma unroll
                for (int ni = 0; ni < 4; ni++)
                    k2[ni] = *(const ulonglong2*)&sK[nb[ni] + dc * 4];
                #pragma unroll
                for (int ni = 0; ni < 4; ni++)
                    #pragma unroll
                    for (int mi = 0; mi < 4; mi++) {
                        ffma2(acc[mi][ni], q2[mi].x, k2[ni].x);
                        ffma2(acc[mi][ni], q2[mi].y, k2[ni].y);
                    }
            }
            // chunk 2: groups 4..8
            {
                ulonglong2 k2[5];
                #pragma unroll
                for (int ni = 0; ni < 5; ni++)
                    k2[ni] = *(const ulonglong2*)&sK[nb[ni + 4] + dc * 4];
                #pragma unroll
                for (int ni = 0; ni < 5; ni++)
                    #pragma unroll
                    for (int mi = 0; mi < 4; mi++) {
                        ffma2(acc[mi][ni + 4], q2[mi].x, k2[ni].x);
                        ffma2(acc[mi][ni + 4], q2[mi].y, k2[ni].y);
                    }
            }
        }
    }
    __syncthreads();   // all QK reads of sK AND sQ done (acc in registers)

    // ---- V: ONE dense bulk load into sK region (phase 1).
    //      Rows n_lo..n_hi-1 contiguous in gmem. Rows < n_lo alias bytes
    //      already written by the padded-K fill (finite), and p=0 there,
    //      so no zeroing is needed (0 * finite = 0).
    if (tid == 0) {
        mbar_arrive_expect(mb, (uint32_t)(n_hi - n_lo) * (DH * 4));
        bulk_load(s2u(&sK[n_lo * DH]),
                  v + base + (size_t)(jn0 + n_lo) * DH,
                  (uint32_t)(n_hi - n_lo) * (DH * 4), mb);
    }

    // ---- epilogue: fixed-shift exp, sum, store p; self-zeroes the row ----
    {
        #pragma unroll
        for (int mi = 0; mi < 4; mi++) {
            const int m = m0 + mi;
            const int i = i0 + m;
            const int jlo = max(0, i - (WIN - 1));
            const int s = (jlo & ~3) - jn0;
            const int off_lo = jlo & 3;
            const int off_hi = i - (jlo & ~3);
            float* rp = sS + m * SROW + 4;

            // head slack [-4, m0-s): stores below cover from max(-4, m0-s)
            const int cnt = min(max(m0 - s + 4, 0), 8);
            if (lane < cnt)
                rp[-4 + lane] = 0.f;

            float sc[9];
            float sum = 0.f;
            #pragma unroll
            for (int ni = 0; ni < 9; ni++) {
                const int off = m0 + lane + 32 * ni - s;
                const bool ok = (off >= off_lo) && (off <= off_hi);
                float e = ok ? __expf(unpk_sum(acc[mi][ni]) * 0.125f) : 0.f;
                sc[ni] = e;
                sum += e;
            }
            #pragma unroll
            for (int o = 16; o; o >>= 1)
                sum += __shfl_xor_sync(0xffffffffu, sum, o);

            const float inv = 1.f / sum;
            #pragma unroll
            for (int ni = 0; ni < 9; ni++) {
                const int off = m0 + lane + 32 * ni - s;
                // stores zeros outside the band too: covers [max(-4,m0-s), 263]
                if ((unsigned)(off + 4) < (unsigned)SROW)
                    rp[off] = sc[ni] * inv;
            }
        }
    }

    // ---- band bulk stores: warp-local rows, issue immediately ----
    __syncwarp();
    if (lane < 4) {
        const int m = m0 + lane;
        const int i = i0 + m;
        const int jlo = max(0, i - (WIN - 1));
        const int jstart4 = jlo & ~3;
        const int jend4 = (i + 4) & ~3;
        fence_async();
        bulk_store(attn + attn_base + (size_t)i * SQ + jstart4,
                   s2u(sS + m * SROW + 4),
                   (uint32_t)(jend4 - jstart4) * 4u);
    }

    mbar_wait(mb, 1);  // V resident (per-warp wait; no CTA sync needed:
                       // this warp's p rows are its own, V is TMA-complete)

    // ---- PV: warp-local. Warp w, rows r0=4w..4w+3; lane = dq + 16*kh.
    //      Each thread: 4 rows x 1 d-quad x half the key range.
    {
        const int dq = lane & 15;         // d cols dq*4..dq*4+3
        const int kh = lane >> 4;         // key half within the warp
        const int r0 = m0;                // same rows as this warp's epilogue

        int sr[4];
        #pragma unroll
        for (int rr = 0; rr < 4; rr++)
            sr[rr] = (max(0, i0 + r0 + rr - (WIN - 1)) & ~3) - jn0;

        const int nbase = sr[3] - 4;            // ≡ 3 mod 4; aligned p4 loads
        const int nend  = r0 + 258;             // inclusive
        const int iters = (nend - nbase + 1) >> 2;
        const int ih    = (iters + 1) >> 1;
        const int itlo  = kh ? ih : 0;
        const int ithi  = kh ? iters : ih;

        const float* rp0 = sS + (r0 + 0) * SROW + 4 - sr[0];
        const float* rp1 = sS + (r0 + 1) * SROW + 4 - sr[1];
        const float* rp2 = sS + (r0 + 2) * SROW + 4 - sr[2];
        const float* rp3 = sS + (r0 + 3) * SROW + 4 - sr[3];

        ull ax[4], az[4];
        #pragma unroll
        for (int rr = 0; rr < 4; rr++) { ax[rr] = 0ULL; az[rr] = 0ULL; }

        #pragma unroll 1
        for (int it = itlo; it < ithi; it++) {
            const int n = nbase + 4 * it;
            const float4 p0 = *(const float4*)&rp0[n];
            const float4 p1 = *(const float4*)&rp1[n];
            const float4 p2 = *(const float4*)&rp2[n];
            const float4 p3 = *(const float4*)&rp3[n];
            #pragma unroll
            for (int c = 0; c < 4; c++) {
                ulonglong2 v2 = *(const ulonglong2*)&sK[(n + c) * DH + dq * 4];
                ull pc0 = pk2((&p0.x)[c]);
                ull pc1 = pk2((&p1.x)[c]);
                ull pc2 = pk2((&p2.x)[c]);
                ull pc3 = pk2((&p3.x)[c]);
                ffma2(ax[0], pc0, v2.x); ffma2(az[0], pc0, v2.y);
                ffma2(ax[1], pc1, v2.x); ffma2(az[1], pc1, v2.y);
                ffma2(ax[2], pc2, v2.x); ffma2(az[2], pc2, v2.y);
                ffma2(ax[3], pc3, v2.x); ffma2(az[3], pc3, v2.y);
            }
        }

        // combine key halves across lane-16 pairs via shfl; lanes<16 stage
        // the out tile into sQ (Q fully consumed by QK).
        #pragma unroll
        for (int rr = 0; rr < 4; rr++) {
            float f0, f1, f2, f3;
            asm("mov.b64 {%0, %1}, %2;" : "=f"(f0), "=f"(f1) : "l"(ax[rr]));
            asm("mov.b64 {%0, %1}, %2;" : "=f"(f2), "=f"(f3) : "l"(az[rr]));
            f0 += __shfl_xor_sync(0xffffffffu, f0, 16);
            f1 += __shfl_xor_sync(0xffffffffu, f1, 16);
            f2 += __shfl_xor_sync(0xffffffffu, f2, 16);
            f3 += __shfl_xor_sync(0xffffffffu, f3, 16);
            if (kh == 0)
                *(float4*)&sQ[(r0 + rr) * DH + dq * 4] =
                    make_float4(f0, f1, f2, f3);
        }
    }
    __syncthreads();   // full out tile staged in sQ

    // ---- out tile: one 16KB bulk store (contiguous [64][64] in gmem) ----
    if (tid == 0) {
        fence_async();
        bulk_store(out + base + (size_t)i0 * DH, s2u(sQ),
                   (uint32_t)(MT * DH * 4));
    }

    // ---- ensure all bulk stores complete before kernel end ----
    asm volatile("cp.async.bulk.commit_group;" ::: "memory");
    asm volatile("cp.async.bulk.wait_group 0;" ::: "memory");
}

extern "C" void kernel_launch(void* const* d_in, const int* in_sizes, int n_in,
                              void* d_out, int out_size)
{
    const float* q = (const float*)d_in[0];
    const float* k = (const float*)d_in[1];
    const float* v = (const float*)d_in[2];

    const int BH = in_sizes[0] / (SQ * DH);   // 32

    float* out  = (float*)d_out;
    float* attn = out + (size_t)BH * SQ * DH;

    cudaFuncSetAttribute(cwa_kernel,
                         cudaFuncAttributeMaxDynamicSharedMemorySize,
                         SM_TOT * (int)sizeof(float));

    dim3 grid(SQ / MT, BH);
    cwa_kernel<<<grid, NTH, SM_TOT * sizeof(float)>>>(q, k, v, out, attn);
    (void)n_in; (void)out_size;
}